// round 1
// baseline (speedup 1.0000x reference)
#include <cuda_runtime.h>

#define N 256
#define BIG 1e9f

// Exact Jonker-Volgenant LAP (min-cost assignment), mirroring the JAX
// reference step-for-step. Single block, 256 threads; thread t owns
// (1-indexed) column j = t+1. Column 0 is the dummy column (always 'used'
// from the first inner step; thread 0 additionally applies its dual updates,
// which matter because p[0] = current row i, so u[i] accumulates delta).
__global__ __launch_bounds__(256, 1)
void lap_jv_kernel(const float* __restrict__ C, float* __restrict__ out) {
    __shared__ float u[N + 1];
    __shared__ float v[N + 1];
    __shared__ float minv[N + 1];
    __shared__ int   p[N + 1];     // p[j] = row matched to column j (0 = free)
    __shared__ int   way[N + 1];
    __shared__ unsigned char used[N + 1];
    __shared__ float wmin[8];
    __shared__ int   widx[8];
    __shared__ int   s_j0;
    __shared__ int   s_j1;
    __shared__ float s_delta;

    const int tid  = threadIdx.x;
    const int j    = tid + 1;          // column 1..256
    const int lane = tid & 31;
    const int warp = tid >> 5;

    // init duals / matching
    u[tid] = 0.0f; v[tid] = 0.0f; p[tid] = 0;
    if (tid == 0) { u[N] = 0.0f; v[N] = 0.0f; p[N] = 0; }
    __syncthreads();

    for (int i = 1; i <= N; ++i) {
        // per-row Dijkstra init
        used[j] = 0; minv[j] = BIG; way[j] = 0;
        if (tid == 0) {
            used[0] = 0; minv[0] = BIG; way[0] = 0;
            p[0] = i; s_j0 = 0;
        }
        __syncthreads();

        // shortest augmenting path loop
        for (;;) {
            const int j0 = s_j0;
            const int i0 = p[j0];          // p is not modified inside this loop
            if (i0 == 0) break;            // consistent across threads (post-sync)
            if (tid == 0) used[j0] = 1;
            __syncthreads();               // used[j0] visible to everyone

            // reduced cost of row i0 at column j; update minv/way
            const float cur = C[(i0 - 1) * N + (j - 1)] - u[i0] - v[j];
            float mv = minv[j];
            if (!used[j] && cur < mv) { mv = cur; minv[j] = cur; way[j] = j0; }

            // argmin over masked minv, first-index tie-break (matches jnp.argmin)
            float val = used[j] ? BIG : mv;
            int   idx = j;
            #pragma unroll
            for (int off = 16; off; off >>= 1) {
                const float ov = __shfl_down_sync(0xFFFFFFFF, val, off);
                const int   oi = __shfl_down_sync(0xFFFFFFFF, idx, off);
                if (ov < val || (ov == val && oi < idx)) { val = ov; idx = oi; }
            }
            if (lane == 0) { wmin[warp] = val; widx[warp] = idx; }
            __syncthreads();
            if (tid == 0) {
                float bv = wmin[0]; int bi = widx[0];
                #pragma unroll
                for (int w = 1; w < 8; ++w) {
                    const float ov = wmin[w]; const int oi = widx[w];
                    if (ov < bv || (ov == bv && oi < bi)) { bv = ov; bi = oi; }
                }
                s_delta = bv; s_j1 = bi;
            }
            __syncthreads();

            // dual / minv updates (scatter u[p[j]] is conflict-free: used
            // columns are matched to pairwise-distinct rows, and p[0]=i is
            // distinct from all of them)
            const float d = s_delta;
            if (used[j]) { u[p[j]] += d; v[j] -= d; }
            else         { minv[j] -= d; }
            if (tid == 0) { u[p[0]] += d; v[0] -= d; s_j0 = s_j1; }
            __syncthreads();
        }

        // augment alternating path back to dummy column 0 (serial, short)
        if (tid == 0) {
            int jj = s_j0;
            while (jj != 0) { const int j1 = way[jj]; p[jj] = p[j1]; jj = j1; }
        }
        __syncthreads();
    }

    // emit 0/1 labelling: out[(p[c+1]-1) * N + c] = 1
    for (int k = tid; k < N * N; k += 256) out[k] = 0.0f;
    __syncthreads();
    const int r = p[j] - 1;
    out[r * N + tid] = 1.0f;
}

extern "C" void kernel_launch(void* const* d_in, const int* in_sizes, int n_in,
                              void* d_out, int out_size) {
    (void)in_sizes; (void)n_in; (void)out_size;
    const float* unaries = (const float*)d_in[0];
    float* out = (float*)d_out;
    lap_jv_kernel<<<1, 256>>>(unaries, out);
}

// round 2
// speedup vs baseline: 1.2084x; 1.2084x over previous
#include <cuda_runtime.h>

#define N 256
#define BIG 1e9f

// Monotone float -> uint mapping (preserves order for min-reduction)
__device__ __forceinline__ unsigned fkey(float f) {
    unsigned b = __float_as_uint(f);
    return (b & 0x80000000u) ? ~b : (b | 0x80000000u);
}

// Single-warp Jonker-Volgenant LAP with register-resident column state and an
// absolute-distance Dijkstra reformulation.
//
// Identity used: in the reference inner loop, u[i0] and v[j] (unused j) are
// always at their row-start values when `cur` is computed, because duals of a
// column's matched row are bumped only starting at the step that column is
// marked used (and it is scanned in that same step). Hence:
//     cur_abs = C[i0-1][j-1] - u0[i0] - v0[j] + Dprev
// with dist[] kept absolute (no per-step delta subtraction), and the per-step
// dual updates collapse into one end-of-row update per used column:
//     amt = Dfinal - mark[j];  v[j] -= amt;  u[p[j]] += amt
// (mark[j] = cumulative delta sum when j was marked used; p taken before
// augmentation). Dummy column 0: u[i] += Dfinal; v[0] is never read.
//
// Thread `lane` owns columns lane*8+1 .. lane*8+8 (contiguous => lowest winner
// lane == lowest column index, matching jnp.argmin's first-index tie-break).
__global__ __launch_bounds__(32, 1)
void lap_jv_warp(const float* __restrict__ C, float* __restrict__ out) {
    __shared__ float u0[N + 1];
    __shared__ int   p[N + 1];      // p[j] = row matched to column j (0 = free)
    __shared__ int   way[N + 1];

    const int lane  = threadIdx.x;
    const int cbase = lane * 8 + 1; // first owned column (1-indexed)

    for (int k = lane; k <= N; k += 32) { u0[k] = 0.0f; p[k] = 0; }
    float v[8], dist[8], mark[8];
    #pragma unroll
    for (int k = 0; k < 8; ++k) v[k] = 0.0f;
    __syncwarp();

    for (int i = 1; i <= N; ++i) {
        #pragma unroll
        for (int k = 0; k < 8; ++k) { dist[k] = BIG; mark[k] = 0.0f; }
        unsigned usedmask = 0;
        float Dsum = 0.0f;          // cumulative delta (== settled min distance)
        int j0 = 0;
        int i0 = i;                 // p[0] = i conceptually; avoid the LDS
        if (lane == 0) p[0] = i;
        int jfree;

        for (;;) {
            // mark j0 used (j0==0 on the first step: owned by nobody; handled
            // at row end via u0[i] += Dfinal)
            #pragma unroll
            for (int k = 0; k < 8; ++k)
                if (cbase + k == j0) { usedmask |= (1u << k); mark[k] = Dsum; }

            // scan row i0: absolute reduced costs at row-start duals
            const float ui = u0[i0];
            const float4 c0 = *(const float4*)&C[(i0 - 1) * N + (cbase - 1)];
            const float4 c1 = *(const float4*)&C[(i0 - 1) * N + (cbase + 3)];
            const float cc[8] = {c0.x, c0.y, c0.z, c0.w, c1.x, c1.y, c1.z, c1.w};
            #pragma unroll
            for (int k = 0; k < 8; ++k) {
                const float cur = cc[k] - ui - v[k] + Dsum;
                if (!((usedmask >> k) & 1u) && cur < dist[k]) {
                    dist[k] = cur;
                    way[cbase + k] = j0;
                }
            }

            // local argmin over the 8 owned columns (strict < keeps first idx)
            float bv = 2.0f * BIG; int bk = 0;
            #pragma unroll
            for (int k = 0; k < 8; ++k) {
                const float val = ((usedmask >> k) & 1u) ? 2.0f * BIG : dist[k];
                if (val < bv) { bv = val; bk = k; }
            }

            // warp argmin: redux on ordered key, lowest-lane tie-break
            const unsigned key  = fkey(bv);
            const unsigned kmin = __reduce_min_sync(0xFFFFFFFFu, key);
            const unsigned ball = __ballot_sync(0xFFFFFFFFu, key == kmin);
            const int wlane = __ffs(ball) - 1;
            Dsum = __shfl_sync(0xFFFFFFFFu, bv, wlane);        // new settled dist
            const int j1 = __shfl_sync(0xFFFFFFFFu, cbase + bk, wlane);

            j0 = j1;
            i0 = p[j1];             // broadcast LDS; doubles as loop-exit test
            if (i0 == 0) { jfree = j1; break; }
        }

        // end-of-row dual updates (pre-augmentation p); conflict-free scatter:
        // used columns are matched to pairwise-distinct rows, all != i
        const float Dfinal = Dsum;
        #pragma unroll
        for (int k = 0; k < 8; ++k) {
            if ((usedmask >> k) & 1u) {
                const float amt = Dfinal - mark[k];
                v[k] -= amt;
                u0[p[cbase + k]] += amt;
            }
        }
        if (lane == 0) u0[i] += Dfinal;   // dummy column 0: p[0] = i, mark = 0
        __syncwarp();                     // p reads done before augmentation

        if (lane == 0) {
            int jj = jfree;
            while (jj != 0) { const int j1 = way[jj]; p[jj] = p[j1]; jj = j1; }
        }
        __syncwarp();
    }

    // emit 0/1 labelling
    const float4 z = make_float4(0.f, 0.f, 0.f, 0.f);
    for (int idx = lane; idx < N * N / 4; idx += 32) ((float4*)out)[idx] = z;
    __syncwarp();
    #pragma unroll
    for (int k = 0; k < 8; ++k) {
        const int col = cbase + k - 1;        // 0-based column
        const int r   = p[col + 1] - 1;       // 0-based matched row
        out[r * N + col] = 1.0f;
    }
}

extern "C" void kernel_launch(void* const* d_in, const int* in_sizes, int n_in,
                              void* d_out, int out_size) {
    (void)in_sizes; (void)n_in; (void)out_size;
    lap_jv_warp<<<1, 32>>>((const float*)d_in[0], (float*)d_out);
}